// round 1
// baseline (speedup 1.0000x reference)
#include <cuda_runtime.h>
#include <math.h>
#include <stdint.h>

// Problem dims (fixed by the dataset)
#define NT 2048      // time steps
#define NB 64        // batch
#define NI 256       // input size
#define NH 512       // hidden size
#define NG 2048      // 4*NH gate columns
#define GRID_B 128   // persistent CTAs (1 per SM, < 148 -> single wave, co-resident)

// Scratch (allocation-free rule: __device__ globals)
__device__ float g_xw[(size_t)NT * NB * NG];   // 1 GiB: precomputed x@Wi + B, [t][b][gatecol]
__device__ float g_h[2 * NH * NB];             // double-buffered h, transposed [k][b]
__device__ unsigned g_bar_count;
__device__ unsigned g_bar_gen;

__device__ __forceinline__ float sigmoidf_(float x) { return 1.0f / (1.0f + expf(-x)); }

// Software grid barrier across GRID_B co-resident CTAs.
__device__ __forceinline__ void grid_barrier() {
    __syncthreads();
    if (threadIdx.x == 0) {
        volatile unsigned* genp = &g_bar_gen;
        unsigned my = *genp;
        __threadfence();                       // release: publish h writes
        if (atomicAdd(&g_bar_count, 1u) == GRID_B - 1) {
            atomicExch(&g_bar_count, 0u);
            __threadfence();
            *genp = my + 1;
        } else {
            while (*genp == my) { __nanosleep(64); }
        }
        __threadfence();                       // acquire
    }
    __syncthreads();
}

// ---------------- Phase 1: xW = x @ Wi + B  (fp32 SIMT tiled GEMM) ----------------
// M=131072 (t*64+b), K=256, N=2048. 128x128 tile, BK=8, 256 threads, 8x8 microtile.
__global__ void __launch_bounds__(256, 2)
xw_gemm_kernel(const float* __restrict__ x, const float* __restrict__ Wi,
               const float* __restrict__ bias) {
    __shared__ float As[8][132];   // +4 pad: conflict-free transpose store
    __shared__ float Bs[8][128];

    const int tid = threadIdx.x;
    const int tx = tid & 15, ty = tid >> 4;
    const int bm = blockIdx.y << 7, bn = blockIdx.x << 7;
    const int lrow = tid >> 1, lk = (tid & 1) << 2;        // A tile loader
    const int brow = tid >> 5, bcol = (tid & 31) << 2;     // B tile loader

    float acc[8][8];
    #pragma unroll
    for (int i = 0; i < 8; i++)
        #pragma unroll
        for (int j = 0; j < 8; j++) acc[i][j] = 0.f;

    for (int kt = 0; kt < NI; kt += 8) {
        float4 av = *reinterpret_cast<const float4*>(x + (size_t)(bm + lrow) * NI + kt + lk);
        float4 bv = *reinterpret_cast<const float4*>(Wi + (size_t)(kt + brow) * NG + bn + bcol);
        As[lk + 0][lrow] = av.x;
        As[lk + 1][lrow] = av.y;
        As[lk + 2][lrow] = av.z;
        As[lk + 3][lrow] = av.w;
        *reinterpret_cast<float4*>(&Bs[brow][bcol]) = bv;
        __syncthreads();
        #pragma unroll
        for (int kk = 0; kk < 8; kk++) {
            float4 t0 = *reinterpret_cast<const float4*>(&As[kk][ty << 3]);
            float4 t1 = *reinterpret_cast<const float4*>(&As[kk][(ty << 3) + 4]);
            float4 t2 = *reinterpret_cast<const float4*>(&Bs[kk][tx << 3]);
            float4 t3 = *reinterpret_cast<const float4*>(&Bs[kk][(tx << 3) + 4]);
            float a[8] = {t0.x, t0.y, t0.z, t0.w, t1.x, t1.y, t1.z, t1.w};
            float b[8] = {t2.x, t2.y, t2.z, t2.w, t3.x, t3.y, t3.z, t3.w};
            #pragma unroll
            for (int i = 0; i < 8; i++)
                #pragma unroll
                for (int j = 0; j < 8; j++)
                    acc[i][j] += a[i] * b[j];
        }
        __syncthreads();
    }

    float4 bb0 = *reinterpret_cast<const float4*>(bias + bn + (tx << 3));
    float4 bb1 = *reinterpret_cast<const float4*>(bias + bn + (tx << 3) + 4);
    const float bb[8] = {bb0.x, bb0.y, bb0.z, bb0.w, bb1.x, bb1.y, bb1.z, bb1.w};
    #pragma unroll
    for (int i = 0; i < 8; i++) {
        size_t row = (size_t)bm + (ty << 3) + i;
        float4 o0 = make_float4(acc[i][0] + bb[0], acc[i][1] + bb[1],
                                acc[i][2] + bb[2], acc[i][3] + bb[3]);
        float4 o1 = make_float4(acc[i][4] + bb[4], acc[i][5] + bb[5],
                                acc[i][6] + bb[6], acc[i][7] + bb[7]);
        *reinterpret_cast<float4*>(g_xw + row * NG + bn + (tx << 3)) = o0;
        *reinterpret_cast<float4*>(g_xw + row * NG + bn + (tx << 3) + 4) = o1;
    }
}

// ---------------- Phase 2: persistent recurrent kernel ----------------
// 128 CTAs x 256 threads. CTA owns 4 hidden units (16 gate columns:
// c_idx = gate*4 + unit -> global col = gate*512 + u_base + unit).
// Per step: stage h[512][64] into SMEM, split-K(8) x (4 col-grp) x (8 b-grp)
// matmul partials, SMEM reduce + add xW, LSTM cell (c in registers), write h.
#define SMEM_B_FLOATS (NH * 16 + NH * NB + 8 * 1024 + 16 * 64)   // 50176 floats = 200704 B

__global__ void __launch_bounds__(256, 1)
lstm_rec_kernel(const float* __restrict__ Wh, float* __restrict__ out, int write_state) {
    extern __shared__ float smem[];
    float* sWh   = smem;                  // [512][16]  Wh slice, resident all steps
    float* shT   = sWh + NH * 16;         // [512][64]  h (k-major)
    float* sRed  = shT + NH * NB;         // [8][1024]  split-K partials
    float* sGate = sRed + 8 * 1024;       // [16][64]   reduced gates

    const int tid = threadIdx.x;
    const int u_base = blockIdx.x << 2;

    // Load this CTA's Wh columns once (stays in SMEM for all 2048 steps).
    for (int idx = tid; idx < NH * 16; idx += 256) {
        int k = idx >> 4, c = idx & 15;
        int col = ((c >> 2) * NH) + u_base + (c & 3);
        sWh[idx] = Wh[(size_t)k * NG + col];
    }
    // Zero h buffer 0 (h_0 = 0); each CTA zeros its own 4 rows.
    {
        int i = tid >> 6, b = tid & 63;
        g_h[(u_base + i) * NB + b] = 0.f;
    }
    __threadfence();
    grid_barrier();

    const int bg = tid & 7;                // batch group (8 batches)
    const int cg = (tid >> 3) & 3;         // column group (4 cols)
    const int s  = tid >> 5;               // split-K slice (64 k's)
    const int eb = tid >> 2, ei = tid & 3; // epilogue (batch, unit)
    float c_reg = 0.f;

    const float4* sWh4 = reinterpret_cast<const float4*>(sWh);
    const float4* shT4 = reinterpret_cast<const float4*>(shT);

    for (int t = 0; t < NT; t++) {
        // Stage h (read buffer t&1) from L2, bypassing L1 (.cg) for coherence.
        const float4* gh4 = reinterpret_cast<const float4*>(g_h + (t & 1) * (NH * NB));
        float4* shTw = reinterpret_cast<float4*>(shT);
        #pragma unroll 8
        for (int j = 0; j < 32; j++)
            shTw[tid + (j << 8)] = __ldcg(gh4 + tid + (j << 8));
        __syncthreads();

        // Split-K matmul partials: acc[col 0..3][batch 0..7]
        float acc[4][8];
        #pragma unroll
        for (int c = 0; c < 4; c++)
            #pragma unroll
            for (int b = 0; b < 8; b++) acc[c][b] = 0.f;

        const int kbeg = s << 6;
        #pragma unroll 4
        for (int k = kbeg; k < kbeg + 64; k++) {
            float4 w  = sWh4[(k << 2) + cg];
            float4 h0 = shT4[(k << 4) + (bg << 1)];
            float4 h1 = shT4[(k << 4) + (bg << 1) + 1];
            float wv[4] = {w.x, w.y, w.z, w.w};
            float hv[8] = {h0.x, h0.y, h0.z, h0.w, h1.x, h1.y, h1.z, h1.w};
            #pragma unroll
            for (int c = 0; c < 4; c++)
                #pragma unroll
                for (int b = 0; b < 8; b++)
                    acc[c][b] += wv[c] * hv[b];
        }
        #pragma unroll
        for (int c = 0; c < 4; c++)
            #pragma unroll
            for (int b = 0; b < 8; b++)
                sRed[(s << 10) + (((cg << 2) + c) << 6) + (bg << 3) + b] = acc[c][b];
        __syncthreads();

        // Reduce 8 partials + add xW[t] -> sGate (4 outputs per thread, vectorized)
        {
            const int o0 = tid << 2;
            float4 sum = *reinterpret_cast<const float4*>(&sRed[o0]);
            #pragma unroll
            for (int ss = 1; ss < 8; ss++) {
                float4 v = *reinterpret_cast<const float4*>(&sRed[(ss << 10) + o0]);
                sum.x += v.x; sum.y += v.y; sum.z += v.z; sum.w += v.w;
            }
            const int c_idx = o0 >> 6;
            const int b0 = o0 & 63;
            const int col = ((c_idx >> 2) * NH) + u_base + (c_idx & 3);
            const float* xwp = g_xw + (size_t)t * (NB * NG) + col;
            sum.x += __ldg(xwp + (size_t)(b0 + 0) * NG);
            sum.y += __ldg(xwp + (size_t)(b0 + 1) * NG);
            sum.z += __ldg(xwp + (size_t)(b0 + 2) * NG);
            sum.w += __ldg(xwp + (size_t)(b0 + 3) * NG);
            *reinterpret_cast<float4*>(&sGate[o0]) = sum;
        }
        __syncthreads();

        // LSTM cell: thread <-> (batch eb, unit ei), c lives in a register.
        {
            float G0 = sGate[((0 * 4 + ei) << 6) + eb];
            float G1 = sGate[((1 * 4 + ei) << 6) + eb];
            float G2 = sGate[((2 * 4 + ei) << 6) + eb];
            float G3 = sGate[((3 * 4 + ei) << 6) + eb];
            float ig = sigmoidf_(G0);
            float fg = sigmoidf_(G1);
            float gg = tanhf(G2);
            float og = sigmoidf_(G3);
            c_reg = fg * c_reg + ig * gg;
            float h = og * tanhf(c_reg);
            int u = u_base + ei;
            out[((size_t)t * NB + eb) * NH + u] = h;
            g_h[((t + 1) & 1) * (NH * NB) + u * NB + eb] = h;   // write buffer (t+1)&1
            if (write_state && t == NT - 1) {
                size_t base = (size_t)NT * NB * NH;
                out[base + (size_t)eb * NH + u] = h;                         // hT
                out[base + (size_t)NB * NH + (size_t)eb * NH + u] = c_reg;   // cT
            }
        }
        __threadfence();
        grid_barrier();
    }
}

extern "C" void kernel_launch(void* const* d_in, const int* in_sizes, int n_in,
                              void* d_out, int out_size) {
    const float* x  = (const float*)d_in[0];   // [T, BS, IN]
    const float* Wi = (const float*)d_in[1];   // [IN, 4H]
    const float* Wh = (const float*)d_in[2];   // [H, 4H]
    const float* B  = (const float*)d_in[3];   // [4H]
    float* out = (float*)d_out;

    const int smem_bytes = SMEM_B_FLOATS * (int)sizeof(float);
    cudaFuncSetAttribute(lstm_rec_kernel, cudaFuncAttributeMaxDynamicSharedMemorySize, smem_bytes);

    // Phase 1: xW = x @ Wi + B
    dim3 gA(NG / 128, (NT * NB) / 128);
    xw_gemm_kernel<<<gA, 256>>>(x, Wi, B);

    // Does the output buffer include (hT, cT) after out[T,BS,H]?
    const long long need_full = (long long)NT * NB * NH + 2LL * NB * NH;
    int write_state = ((long long)out_size >= need_full) ? 1 : 0;

    // Phase 2: persistent recurrence
    lstm_rec_kernel<<<GRID_B, 256, smem_bytes>>>(Wh, out, write_state);
}